// round 2
// baseline (speedup 1.0000x reference)
#include <cuda_runtime.h>
#include <math.h>

#define DIN 128
#define DINPAD 132
#define DQK 64
#define QPAD 68
#define KPAD 65
#define NMAX 8192
#define NEGM (-1000000.0f)
#define MARGIN 65536.0f

// scratch: projected k (key @ Wk + bk) for all rows
__device__ float g_k[NMAX * DQK];

// ---------------- kernel 1: k_all = key @ Wk + bk ----------------
__global__ void proj_k_kernel(const float* __restrict__ key,
                              const float* __restrict__ Wk,
                              const float* __restrict__ bk,
                              int n) {
  extern __shared__ float sm[];
  float* sW = sm;                    // [DIN][DQK]
  float* sX = sm + DIN * DQK;        // [32][DINPAD]
  int tid = threadIdx.x;
  int r0 = blockIdx.x * 32;
  for (int i = tid; i < DIN * DQK; i += 256) sW[i] = Wk[i];
  for (int i = tid; i < 32 * DIN; i += 256) {
    int r = i >> 7, c = i & 127;
    sX[r * DINPAD + c] = (r0 + r < n) ? key[(size_t)(r0 + r) * DIN + c] : 0.f;
  }
  __syncthreads();
  int r = tid >> 3, cg = tid & 7;
  if (r0 + r >= n) return;
  float acc[8];
#pragma unroll
  for (int j = 0; j < 8; j++) acc[j] = bk[cg + 8 * j];
  for (int kk = 0; kk < DIN; kk++) {
    float x = sX[r * DINPAD + kk];
#pragma unroll
    for (int j = 0; j < 8; j++) acc[j] = fmaf(x, sW[kk * DQK + cg + 8 * j], acc[j]);
  }
#pragma unroll
  for (int j = 0; j < 8; j++) g_k[(size_t)(r0 + r) * DQK + cg + 8 * j] = acc[j];
}

// ---------------- block reductions (256 threads, scr has >=256 floats) ----
__device__ __forceinline__ float blockReduceMax256(float v, float* scr, int tid) {
  scr[tid] = v;
  __syncthreads();
  for (int s = 128; s > 0; s >>= 1) {
    if (tid < s) scr[tid] = fmaxf(scr[tid], scr[tid + s]);
    __syncthreads();
  }
  float r = scr[0];
  __syncthreads();
  return r;
}
__device__ __forceinline__ float blockReduceSum256(float v, float* scr, int tid) {
  scr[tid] = v;
  __syncthreads();
  for (int s = 128; s > 0; s >>= 1) {
    if (tid < s) scr[tid] = scr[tid] + scr[tid + s];
    __syncthreads();
  }
  float r = scr[0];
  __syncthreads();
  return r;
}

// smem layout (floats)
#define OFF_QIN 0                      // 32*DINPAD = 4224
#define OFF_BIG 4224                   // 8192 (Wq, then k-tile)
#define OFF_Q 12416                    // 32*QPAD = 2176
#define OFF_RED 14592                  // 256
#define OFF_QN 14848                   // 32
#define OFF_BMP 14880                  // 256
#define OFF_T 15136                    // 32
#define OFF_FND 15168                  // 32 ints
#define OFF_FLG 15200                  // 8
#define SMEM2_FLOATS 15208

// ---------------- kernel 2: main ----------------
__global__ void attn_main_kernel(const float* __restrict__ query,
                                 const float* __restrict__ value,
                                 const float* __restrict__ bmat,
                                 const int* __restrict__ ptr,
                                 const float* __restrict__ Wq,
                                 const float* __restrict__ bq,
                                 const float* __restrict__ Wv,
                                 const float* __restrict__ bv,
                                 float* __restrict__ out,
                                 int n, int g) {
  extern __shared__ float sm[];
  float* sQin = sm + OFF_QIN;
  float* sBig = sm + OFF_BIG;
  float* sQ = sm + OFF_Q;
  float* sRed = sm + OFF_RED;
  float* sQn = sm + OFF_QN;
  float* sBmp = sm + OFF_BMP;
  float* sT = sm + OFF_T;
  int* sFnd = (int*)(sm + OFF_FND);
  int* sFlg = (int*)(sm + OFF_FLG);

  int tid = threadIdx.x;
  int r0 = blockIdx.x * 32;
  if (r0 >= n) return;
  int nr = min(32, n - r0);

  // segment of first row: max i with ptr[i] <= r0
  int seg = 0;
  for (int i = 1; i < g; i++)
    if (ptr[i] <= r0) seg = i;
  int s0 = ptr[seg], s1 = ptr[seg + 1];
  bool aligned = (r0 >= s0) && (r0 + nr <= s1);

  // ---- compute q for this CTA's rows (always needed) ----
  for (int i = tid; i < DIN * DQK; i += 256) sBig[i] = Wq[i];
  for (int i = tid; i < 32 * DIN; i += 256) {
    int r = i >> 7, c = i & 127;
    sQin[r * DINPAD + c] = (r0 + r < n) ? query[(size_t)(r0 + r) * DIN + c] : 0.f;
  }
  __syncthreads();
  {
    int r = tid >> 3, cg = tid & 7;
    float acc[8];
#pragma unroll
    for (int j = 0; j < 8; j++) acc[j] = bq[cg + 8 * j];
    for (int kk = 0; kk < DIN; kk++) {
      float x = sQin[r * DINPAD + kk];
#pragma unroll
      for (int j = 0; j < 8; j++) acc[j] = fmaf(x, sBig[kk * DQK + cg + 8 * j], acc[j]);
    }
#pragma unroll
    for (int j = 0; j < 8; j++) sQ[r * QPAD + cg + 8 * j] = acc[j];
  }
  __syncthreads();

  // ---- fast path: prove all rows' in-block exps underflow in the reference ----
  int c0 = -1;
  if (aligned) {
    if (s1 + 64 <= n) c0 = s1;
    else if (s0 >= 64) c0 = s0 - 64;
  }

  if (c0 >= 0) {
    if (tid == 0) { sFlg[0] = 0; sFlg[1] = 0; }
    if (tid < 32) sFnd[tid] = (tid >= nr) ? 1 : 0;
    __syncthreads();

    // |q_r|
    if (tid < 32) {
      float s = 0.f;
      for (int d = 0; d < DQK; d++) {
        float v = sQ[tid * QPAD + d];
        s = fmaf(v, v, s);
      }
      sQn[tid] = sqrtf(s);
    }
    // max in-block |k_c|^2
    {
      float mx = 0.f;
      for (int c = s0 + tid; c < s1; c += 256) {
        float s = 0.f;
        const float* kr = g_k + (size_t)c * DQK;
        for (int d = 0; d < DQK; d++) s = fmaf(kr[d], kr[d], s);
        mx = fmaxf(mx, s);
      }
      atomicMax(&sFlg[1], __float_as_int(mx));  // mx >= 0 -> int compare valid
    }
    // per-row max of in-block b
    {
      int r = tid >> 3, cg = tid & 7;
      float mx = -3.0e38f;
      if (r < nr) {
        const float* brow = bmat + (size_t)(r0 + r) * n;
        for (int c = s0 + cg; c < s1; c += 8) mx = fmaxf(mx, brow[c]);
      }
      sBmp[r * 8 + cg] = mx;
    }
    __syncthreads();
    if (tid < 32) {
      float mx = sBmp[tid * 8];
      for (int j = 1; j < 8; j++) mx = fmaxf(mx, sBmp[tid * 8 + j]);
      float Kn = sqrtf(__int_as_float(sFlg[1]));
      sT[tid] = sQn[tid] * Kn * 0.125f + mx + MARGIN;  // upper bound of in-block score + margin
    }
    __syncthreads();

    // load off-block k tile [64][DQK] (reuse sBig)
    for (int i = tid; i < 64 * DQK; i += 256) {
      int c = i >> 6, d = i & 63;
      sBig[c * KPAD + d] = g_k[(size_t)(c0 + c) * DQK + d];
    }
    __syncthreads();

    // scan 64 off-block columns per row
    {
      int r = tid >> 3, cg = tid & 7;
      if (r < nr) {
        float dot[8] = {0, 0, 0, 0, 0, 0, 0, 0};
        const float* qrow = sQ + r * QPAD;
        for (int kk = 0; kk < DQK; kk++) {
          float qv = qrow[kk];
#pragma unroll
          for (int j = 0; j < 8; j++)
            dot[j] = fmaf(qv, sBig[(cg + 8 * j) * KPAD + kk], dot[j]);
        }
        const float* brow = bmat + (size_t)(r0 + r) * n + c0;
        float Tr = sT[r];
        int fnd = 0;
#pragma unroll
        for (int j = 0; j < 8; j++) {
          int c = cg + 8 * j;
          float s = NEGM * (dot[j] * 0.125f + brow[c]);
          fnd |= (s > Tr) ? 1 : 0;
        }
        if (fnd) sFnd[r] = 1;  // benign race, same value
      }
    }
    __syncthreads();
    if (tid == 0) {
      int all = 1;
      for (int r = 0; r < 32; r++) all &= sFnd[r];
      sFlg[0] = all;
    }
    __syncthreads();
    if (sFlg[0]) {
      // proven: every in-block softmax weight underflows to exactly 0 -> rows are 0
      for (int i = tid; i < nr * DQK; i += 256) out[(size_t)r0 * DQK + i] = 0.f;
      return;
    }
  }

  // ---------------- honest streaming fallback (per row, any ptr layout) ----
  for (int rr = 0; rr < nr; rr++) {
    int row = r0 + rr;
    int sg = 0;
    for (int i = 1; i < g; i++)
      if (ptr[i] <= row) sg = i;
    int rs0 = ptr[sg], rs1 = ptr[sg + 1];
    const float* qrow = sQ + rr * QPAD;
    const float* brow = bmat + (size_t)row * n;

    // pass 1: row max of masked scores
    float m = -3.0e38f;
    for (int c = tid; c < n; c += 256) {
      float dot = 0.f;
      const float* kr = g_k + (size_t)c * DQK;
      for (int d = 0; d < DQK; d++) dot = fmaf(qrow[d], kr[d], dot);
      float s = dot * 0.125f + brow[c];
      if (!(c >= rs0 && c < rs1)) s *= NEGM;
      m = fmaxf(m, s);
    }
    m = blockReduceMax256(m, sRed, tid);

    // pass 2: denominator
    float dsum = 0.f;
    for (int c = tid; c < n; c += 256) {
      float dot = 0.f;
      const float* kr = g_k + (size_t)c * DQK;
      for (int d = 0; d < DQK; d++) dot = fmaf(qrow[d], kr[d], dot);
      float s = dot * 0.125f + brow[c];
      if (!(c >= rs0 && c < rs1)) s *= NEGM;
      dsum += expf(s - m);
    }
    float D = blockReduceSum256(dsum, sRed, tid);

    // pass 3: numerator over in-block cols, chunked; v recomputed on the fly
    float o = 0.f;
    for (int base = rs0; base < rs1; base += 256) {
      int c = base + tid;
      float w = 0.f;
      if (c < rs1) {
        float dot = 0.f;
        const float* kr = g_k + (size_t)c * DQK;
        for (int d = 0; d < DQK; d++) dot = fmaf(qrow[d], kr[d], dot);
        float s = dot * 0.125f + brow[c];  // in-block: mask = 1
        w = expf(s - m);
      }
      sRed[tid] = w;
      __syncthreads();
      int lim = min(256, rs1 - base);
      if (tid < DQK) {
        for (int cc = 0; cc < lim; cc++) {
          int c2 = base + cc;
          float vv = bv[tid];
          const float* vr = value + (size_t)c2 * DIN;
          for (int kk = 0; kk < DIN; kk++) vv = fmaf(vr[kk], Wv[kk * DQK + tid], vv);
          o = fmaf(sRed[cc], vv, o);
        }
      }
      __syncthreads();
    }
    if (tid < DQK) out[(size_t)row * DQK + tid] = o / D;
    __syncthreads();
  }
}

extern "C" void kernel_launch(void* const* d_in, const int* in_sizes, int n_in,
                              void* d_out, int out_size) {
  const float* query = (const float*)d_in[0];
  const float* key = (const float*)d_in[1];
  const float* value = (const float*)d_in[2];
  const float* bmat = (const float*)d_in[3];
  const int* ptr = (const int*)d_in[4];
  const float* Wq = (const float*)d_in[5];
  const float* bq = (const float*)d_in[6];
  const float* Wk = (const float*)d_in[7];
  const float* bk = (const float*)d_in[8];
  const float* Wv = (const float*)d_in[9];
  const float* bv = (const float*)d_in[10];
  float* out = (float*)d_out;

  int n = in_sizes[0] / DIN;
  int g = in_sizes[4] - 1;
  int nblk = (n + 31) / 32;

  size_t sm1 = (size_t)(DIN * DQK + 32 * DINPAD) * sizeof(float);
  size_t sm2 = (size_t)SMEM2_FLOATS * sizeof(float);
  cudaFuncSetAttribute(proj_k_kernel, cudaFuncAttributeMaxDynamicSharedMemorySize, (int)sm1);
  cudaFuncSetAttribute(attn_main_kernel, cudaFuncAttributeMaxDynamicSharedMemorySize, (int)sm2);

  proj_k_kernel<<<nblk, 256, sm1>>>(key, Wk, bk, n);
  attn_main_kernel<<<nblk, 256, sm2>>>(query, value, bmat, ptr, Wq, bq, Wv, bv, out, n, g);
}

// round 4
// speedup vs baseline: 1.4377x; 1.4377x over previous
#include <cuda_runtime.h>
#include <math.h>

#define DIN 128
#define DQK 64
#define NMAX 8192
#define NEGM (-1000000.0f)
#define MARGIN 65536.0f

// scratch
__device__ float g_q[NMAX * DQK];
__device__ float g_k[NMAX * DQK];
__device__ float g_qn[NMAX];          // |q_row|
__device__ float g_kmax[NMAX / 32];   // max |k|^2 per 32-row chunk

// ================= kernel A: project q and k, emit norms =================
// grid = 2*nblk: bx<nblk -> q rows, else k rows. 256 threads.
__global__ void proj_kernel(const float* __restrict__ query,
                            const float* __restrict__ key,
                            const float* __restrict__ Wq,
                            const float* __restrict__ bq,
                            const float* __restrict__ Wk,
                            const float* __restrict__ bk,
                            int n, int nblk) {
  extern __shared__ float sm[];
  float* sW = sm;                 // 128*64 = 8192
  float* sX = sm + 8192;          // 32*132 = 4224
  float* sRed = sm + 8192 + 4224; // 32
  int tid = threadIdx.x;
  int bx = blockIdx.x;
  bool isQ = bx < nblk;
  int cb = isQ ? bx : bx - nblk;
  int r0 = cb * 32;
  const float* X = isQ ? query : key;
  const float* W = isQ ? Wq : Wk;
  const float* bias = isQ ? bq : bk;
  float* outp = isQ ? g_q : g_k;

  const float4* W4 = (const float4*)W;
  float4* sW4 = (float4*)sW;
#pragma unroll
  for (int i = tid; i < 2048; i += 256) sW4[i] = W4[i];
  for (int i = tid; i < 1024; i += 256) {
    int r = i >> 5, c4 = i & 31;
    float4 v = make_float4(0.f, 0.f, 0.f, 0.f);
    if (r0 + r < n) v = ((const float4*)(X + (size_t)(r0 + r) * DIN))[c4];
    ((float4*)sX)[r * 33 + c4] = v;  // 132-float padded rows
  }
  __syncthreads();

  int r = tid >> 3, cg = tid & 7;  // thread computes cols cg*8 .. cg*8+7 of row r
  float acc[8];
#pragma unroll
  for (int j = 0; j < 8; j++) acc[j] = bias[cg * 8 + j];
  const float* xr = sX + r * 132;
#pragma unroll 4
  for (int kk = 0; kk < DIN; kk++) {
    float x = xr[kk];
    float4 w0 = *(const float4*)(sW + kk * DQK + cg * 8);
    float4 w1 = *(const float4*)(sW + kk * DQK + cg * 8 + 4);
    acc[0] = fmaf(x, w0.x, acc[0]);
    acc[1] = fmaf(x, w0.y, acc[1]);
    acc[2] = fmaf(x, w0.z, acc[2]);
    acc[3] = fmaf(x, w0.w, acc[3]);
    acc[4] = fmaf(x, w1.x, acc[4]);
    acc[5] = fmaf(x, w1.y, acc[5]);
    acc[6] = fmaf(x, w1.z, acc[6]);
    acc[7] = fmaf(x, w1.w, acc[7]);
  }
  if (r0 + r < n) {
    float4 o0 = make_float4(acc[0], acc[1], acc[2], acc[3]);
    float4 o1 = make_float4(acc[4], acc[5], acc[6], acc[7]);
    float* dst = outp + (size_t)(r0 + r) * DQK + cg * 8;
    *(float4*)dst = o0;
    *(float4*)(dst + 4) = o1;
  }
  // row sum of squares across the 8 threads of this row (consecutive lanes)
  float ss = 0.f;
#pragma unroll
  for (int j = 0; j < 8; j++) ss = fmaf(acc[j], acc[j], ss);
  ss += __shfl_xor_sync(0xffffffffu, ss, 1);
  ss += __shfl_xor_sync(0xffffffffu, ss, 2);
  ss += __shfl_xor_sync(0xffffffffu, ss, 4);
  if (isQ) {
    if (cg == 0 && r0 + r < n) g_qn[r0 + r] = sqrtf(ss);
  } else {
    // max |k|^2 over the 32 rows of this chunk (upper bound; padded rows only add bias^2)
    float m = ss;
    m = fmaxf(m, __shfl_xor_sync(0xffffffffu, m, 8));
    m = fmaxf(m, __shfl_xor_sync(0xffffffffu, m, 16));
    if ((tid & 31) == 0) sRed[tid >> 5] = m;
    __syncthreads();
    if (tid == 0) {
      float mm = sRed[0];
      for (int i = 1; i < 8; i++) mm = fmaxf(mm, sRed[i]);
      g_kmax[cb] = mm;
    }
  }
}

// ================= kernel B smem layout (floats) =================
#define OFF_Q 0        // 32*68 = 2176
#define OFF_K 2176     // 64*68 = 4352
#define OFF_RED 6528   // 256
#define OFF_QN 6784    // 32
#define OFF_T 6816     // 32
#define OFF_FND 6848   // 32
#define OFF_FLG 6880   // 8
#define OFF_PTR 6888   // 66 ints
#define SMEMB_FLOATS 6956

__device__ __forceinline__ float blockReduceMax256(float v, float* scr, int tid) {
  scr[tid] = v;
  __syncthreads();
  for (int s = 128; s > 0; s >>= 1) {
    if (tid < s) scr[tid] = fmaxf(scr[tid], scr[tid + s]);
    __syncthreads();
  }
  float r = scr[0];
  __syncthreads();
  return r;
}
__device__ __forceinline__ float blockReduceSum256(float v, float* scr, int tid) {
  scr[tid] = v;
  __syncthreads();
  for (int s = 128; s > 0; s >>= 1) {
    if (tid < s) scr[tid] = scr[tid] + scr[tid + s];
    __syncthreads();
  }
  float r = scr[0];
  __syncthreads();
  return r;
}

// ================= kernel B: underflow proof + zero write =================
__global__ void proof_kernel(const float* __restrict__ value,
                             const float* __restrict__ bmat,
                             const int* __restrict__ ptr,
                             const float* __restrict__ Wv,
                             const float* __restrict__ bv,
                             float* __restrict__ out,
                             int n, int g) {
  extern __shared__ float sm[];
  float* sQ = sm + OFF_Q;
  float* sK = sm + OFF_K;
  float* sRed = sm + OFF_RED;
  float* sQn = sm + OFF_QN;
  float* sT = sm + OFF_T;
  int* sFnd = (int*)(sm + OFF_FND);
  int* sFlg = (int*)(sm + OFF_FLG);
  int* sPtr = (int*)(sm + OFF_PTR);

  int tid = threadIdx.x;
  int r0 = blockIdx.x * 32;
  if (r0 >= n) return;
  int nr = min(32, n - r0);

  for (int i = tid; i <= g; i += 256) sPtr[i] = ptr[i];
  // load this CTA's q rows [32][64] -> padded [32][68]
  {
    const float4* gq4 = (const float4*)(g_q + (size_t)r0 * DQK);
    for (int i = tid; i < 512; i += 256) {
      int rr = i >> 4, c4 = i & 15;
      float4 v = make_float4(0.f, 0.f, 0.f, 0.f);
      if (r0 + rr < n) v = gq4[i];
      ((float4*)sQ)[rr * 17 + c4] = v;
    }
  }
  if (tid == 0) { sFlg[0] = 0; sFlg[1] = 0; }
  if (tid < 32) sFnd[tid] = (tid >= nr) ? 1 : 0;
  __syncthreads();

  int seg = 0;
  for (int i = 1; i < g; i++)
    if (sPtr[i] <= r0) seg = i;
  int s0 = sPtr[seg], s1 = sPtr[seg + 1];
  bool aligned = (r0 >= s0) && (r0 + nr <= s1);

  int c0 = -1;
  if (aligned) {
    if (s1 + 64 <= n) c0 = s1;
    else if (s0 >= 64) c0 = s0 - 64;
  }

  if (c0 >= 0) {
    if (tid < nr) sQn[tid] = g_qn[r0 + tid];

    // max in-block |k|^2 (chunk table if 32-aligned, else honest rescan)
    if ((s0 & 31) == 0 && (s1 & 31) == 0) {
      float mx = 0.f;
      for (int ch = (s0 >> 5) + tid; ch < (s1 >> 5); ch += 256) mx = fmaxf(mx, g_kmax[ch]);
      if (mx > 0.f) atomicMax(&sFlg[1], __float_as_int(mx));
    } else {
      float mx = 0.f;
      for (int c = s0 + tid; c < s1; c += 256) {
        float s = 0.f;
        const float* kr = g_k + (size_t)c * DQK;
        for (int d = 0; d < DQK; d++) s = fmaf(kr[d], kr[d], s);
        mx = fmaxf(mx, s);
      }
      if (mx > 0.f) atomicMax(&sFlg[1], __float_as_int(mx));
    }

    // load off-block k tile [64][64] -> padded [64][68]
    {
      const float4* gk4 = (const float4*)(g_k + (size_t)c0 * DQK);
      for (int i = tid; i < 1024; i += 256) {
        int rr = i >> 4, c4 = i & 15;
        ((float4*)sK)[rr * 17 + c4] = gk4[i];
      }
    }

    // per-row max of in-block b: warp w -> rows 4w..4w+3, coalesced lanes
    {
      int w = tid >> 5, lane = tid & 31;
      for (int rr = w * 4; rr < w * 4 + 4; rr++) {
        if (rr < nr) {
          float mx = -3.0e38f;
          const float* brow = bmat + (size_t)(r0 + rr) * n;
          for (int c = s0 + lane; c < s1; c += 32) mx = fmaxf(mx, brow[c]);
          mx = fmaxf(mx, __shfl_xor_sync(0xffffffffu, mx, 16));
          mx = fmaxf(mx, __shfl_xor_sync(0xffffffffu, mx, 8));
          mx = fmaxf(mx, __shfl_xor_sync(0xffffffffu, mx, 4));
          mx = fmaxf(mx, __shfl_xor_sync(0xffffffffu, mx, 2));
          mx = fmaxf(mx, __shfl_xor_sync(0xffffffffu, mx, 1));
          if (lane == 0) sT[rr] = mx;
        }
      }
    }
    __syncthreads();

    if (tid < 32) {
      float kn = sqrtf(__int_as_float(sFlg[1]));
      float T = sQn[tid] * kn * 0.125f + sT[tid] + MARGIN;
      sT[tid] = -1.0e-6f * T;  // test becomes: dot/8 + b < sT[r]
    }
    __syncthreads();

    // scan 64 off-block columns per row; col = cg + 8j (conflict-free stride)
    {
      int rr = tid >> 3, cg = tid & 7;
      if (rr < nr) {
        float dot[8] = {0, 0, 0, 0, 0, 0, 0, 0};
        const float* qrow = sQ + rr * 68;
#pragma unroll 2
        for (int kk = 0; kk < DQK; kk++) {
          float qv = qrow[kk];
#pragma unroll
          for (int j = 0; j < 8; j++)
            dot[j] = fmaf(qv, sK[(cg + 8 * j) * 68 + kk], dot[j]);
        }
        const float* brow = bmat + (size_t)(r0 + rr) * n + c0;
        float u = sT[rr];
        int f = 0;
#pragma unroll
        for (int j = 0; j < 8; j++) {
          float dv = dot[j] * 0.125f + brow[cg + 8 * j];
          f |= (dv < u) ? 1 : 0;
        }
        if (f) sFnd[rr] = 1;  // benign race, same value
      }
    }
    __syncthreads();
    if (tid < 32) {
      unsigned bal = __ballot_sync(0xffffffffu, sFnd[tid] != 0);
      if (tid == 0) sFlg[0] = (bal == 0xffffffffu) ? 1 : 0;
    }
    __syncthreads();
    if (sFlg[0]) {
      // proven: reference in-block exps underflow to 0 for all rows -> output 0
      float4 z = make_float4(0.f, 0.f, 0.f, 0.f);
      float4* o4 = (float4*)(out + (size_t)r0 * DQK);
      for (int i = tid; i < nr * 16; i += 256) o4[i] = z;
      return;
    }
  }

  // ================= honest streaming fallback (any ptr layout) =========
  for (int rr = 0; rr < nr; rr++) {
    int row = r0 + rr;
    int sg = 0;
    for (int i = 1; i < g; i++)
      if (sPtr[i] <= row) sg = i;
    int rs0 = sPtr[sg], rs1 = sPtr[sg + 1];
    const float* qrow = sQ + rr * 68;
    const float* brow = bmat + (size_t)row * n;

    float m = -3.0e38f;
    for (int c = tid; c < n; c += 256) {
      float dot = 0.f;
      const float* kr = g_k + (size_t)c * DQK;
      for (int d = 0; d < DQK; d++) dot = fmaf(qrow[d], kr[d], dot);
      float s = dot * 0.125f + brow[c];
      if (!(c >= rs0 && c < rs1)) s *= NEGM;
      m = fmaxf(m, s);
    }
    m = blockReduceMax256(m, sRed, tid);

    float dsum = 0.f;
    for (int c = tid; c < n; c += 256) {
      float dot = 0.f;
      const float* kr = g_k + (size_t)c * DQK;
      for (int d = 0; d < DQK; d++) dot = fmaf(qrow[d], kr[d], dot);
      float s = dot * 0.125f + brow[c];
      if (!(c >= rs0 && c < rs1)) s *= NEGM;
      dsum += expf(s - m);
    }
    float D = blockReduceSum256(dsum, sRed, tid);

    float o = 0.f;
    for (int base = rs0; base < rs1; base += 256) {
      int c = base + tid;
      float w = 0.f;
      if (c < rs1) {
        float dot = 0.f;
        const float* kr = g_k + (size_t)c * DQK;
        for (int d = 0; d < DQK; d++) dot = fmaf(qrow[d], kr[d], dot);
        float s = dot * 0.125f + brow[c];
        w = expf(s - m);
      }
      sRed[tid] = w;
      __syncthreads();
      int lim = min(256, rs1 - base);
      if (tid < DQK) {
        for (int cc = 0; cc < lim; cc++) {
          int c2 = base + cc;
          float vv = bv[tid];
          const float* vr = value + (size_t)c2 * DIN;
          for (int kk = 0; kk < DIN; kk++) vv = fmaf(vr[kk], Wv[kk * DQK + tid], vv);
          o = fmaf(sRed[cc], vv, o);
        }
      }
      __syncthreads();
    }
    if (tid < DQK) out[(size_t)row * DQK + tid] = o / D;
    __syncthreads();
  }
}

extern "C" void kernel_launch(void* const* d_in, const int* in_sizes, int n_in,
                              void* d_out, int out_size) {
  const float* query = (const float*)d_in[0];
  const float* key = (const float*)d_in[1];
  const float* value = (const float*)d_in[2];
  const float* bmat = (const float*)d_in[3];
  const int* ptr = (const int*)d_in[4];
  const float* Wq = (const float*)d_in[5];
  const float* bq = (const float*)d_in[6];
  const float* Wk = (const float*)d_in[7];
  const float* bk = (const float*)d_in[8];
  const float* Wv = (const float*)d_in[9];
  const float* bv = (const float*)d_in[10];
  float* out = (float*)d_out;

  int n = in_sizes[0] / DIN;
  int g = in_sizes[4] - 1;
  int nblk = (n + 31) / 32;

  size_t smA = (size_t)(8192 + 4224 + 32) * sizeof(float);
  size_t smB = (size_t)SMEMB_FLOATS * sizeof(float);
  cudaFuncSetAttribute(proj_kernel, cudaFuncAttributeMaxDynamicSharedMemorySize, (int)smA);
  cudaFuncSetAttribute(proof_kernel, cudaFuncAttributeMaxDynamicSharedMemorySize, (int)smB);

  proj_kernel<<<2 * nblk, 256, smA>>>(query, key, Wq, bq, Wk, bk, n, nblk);
  proof_kernel<<<nblk, 256, smB>>>(value, bmat, ptr, Wv, bv, out, n, g);
}